// round 1
// baseline (speedup 1.0000x reference)
#include <cuda_runtime.h>
#include <math.h>

#define N_NODES 50000
#define N_EDGES 800000
#define NFEAT   512
#define NHID    256
#define NCLASS  128
#define N_UV    2048

// ---------------- scratch (device globals; no allocation allowed) ----------------
__device__ float g_support1[N_NODES * NHID];    // x @ W1
__device__ float g_h[N_NODES * NHID];           // relu(A@support1 + b1)
__device__ float g_support2[N_NODES * NCLASS];  // h @ W2
__device__ float g_z[N_NODES * NCLASS];         // A@support2 + b2
__device__ float g_zu[N_UV * NCLASS];
__device__ float g_zv[N_UV * NCLASS];
__device__ int   g_rowptr[N_NODES + 1];

// ---------------- row pointer build (adj_row is sorted) ----------------
__global__ void build_rowptr_kernel(const int* __restrict__ adj_row) {
    int i = blockIdx.x * blockDim.x + threadIdx.x;
    if (i > N_NODES) return;
    int lo = 0, hi = N_EDGES;               // first e with adj_row[e] >= i
    while (lo < hi) {
        int mid = (lo + hi) >> 1;
        if (adj_row[mid] < i) lo = mid + 1; else hi = mid;
    }
    g_rowptr[i] = lo;
}

// ---------------- SGEMM NN: C[M,N] = A[M,K] @ B[K,N], fp32 ----------------
// BM=BN=128, BK=8, 8x8 micro-tile, 256 threads. Guards only on M (50000).
__global__ __launch_bounds__(256) void sgemm_nn_kernel(
    const float* __restrict__ A, const float* __restrict__ B,
    float* __restrict__ C, int M, int N, int K)
{
    constexpr int BM = 128, BN = 128, BK = 8, TM = 8, TN = 8;
    __shared__ float As[BK][BM];
    __shared__ float Bs[BK][BN];

    int tid = threadIdx.x;
    int bm = blockIdx.y * BM;
    int bn = blockIdx.x * BN;
    int tx = tid % (BN / TN);   // 0..15
    int ty = tid / (BN / TN);   // 0..15

    float acc[TM][TN];
#pragma unroll
    for (int i = 0; i < TM; i++)
#pragma unroll
        for (int j = 0; j < TN; j++) acc[i][j] = 0.f;

    int a_row = tid >> 1;             // 0..127
    int a_col = (tid & 1) * 4;        // 0 or 4
    int b_row = tid >> 5;             // 0..7
    int b_col = (tid & 31) * 4;       // 0..124

    for (int k0 = 0; k0 < K; k0 += BK) {
        float4 av = make_float4(0.f, 0.f, 0.f, 0.f);
        int gr = bm + a_row;
        if (gr < M) av = *reinterpret_cast<const float4*>(&A[(size_t)gr * K + k0 + a_col]);
        As[a_col + 0][a_row] = av.x;
        As[a_col + 1][a_row] = av.y;
        As[a_col + 2][a_row] = av.z;
        As[a_col + 3][a_row] = av.w;

        float4 bv = *reinterpret_cast<const float4*>(&B[(size_t)(k0 + b_row) * N + bn + b_col]);
        *reinterpret_cast<float4*>(&Bs[b_row][b_col]) = bv;
        __syncthreads();

#pragma unroll
        for (int kk = 0; kk < BK; kk++) {
            float ra[TM], rb[TN];
#pragma unroll
            for (int i = 0; i < TM; i++) ra[i] = As[kk][ty * TM + i];
#pragma unroll
            for (int j = 0; j < TN; j++) rb[j] = Bs[kk][tx * TN + j];
#pragma unroll
            for (int i = 0; i < TM; i++)
#pragma unroll
                for (int j = 0; j < TN; j++)
                    acc[i][j] = fmaf(ra[i], rb[j], acc[i][j]);
        }
        __syncthreads();
    }

#pragma unroll
    for (int i = 0; i < TM; i++) {
        int r = bm + ty * TM + i;
        if (r >= M) continue;
#pragma unroll
        for (int j = 0; j < TN; j += 4) {
            float4 v = make_float4(acc[i][j], acc[i][j + 1], acc[i][j + 2], acc[i][j + 3]);
            *reinterpret_cast<float4*>(&C[(size_t)r * N + bn + tx * TN + j]) = v;
        }
    }
}

// ---------------- SGEMM NT + sigmoid: C[M,N] = sigmoid(A[M,K] @ B[N,K]^T) ----------------
// M=N=2048, K=128 — all divisible, no guards.
__global__ __launch_bounds__(256) void sgemm_nt_sigmoid_kernel(
    const float* __restrict__ A, const float* __restrict__ B,
    float* __restrict__ C, int M, int N, int K)
{
    constexpr int BM = 128, BN = 128, BK = 8, TM = 8, TN = 8;
    __shared__ float As[BK][BM];
    __shared__ float Bs[BK][BN];

    int tid = threadIdx.x;
    int bm = blockIdx.y * BM;
    int bn = blockIdx.x * BN;
    int tx = tid % (BN / TN);
    int ty = tid / (BN / TN);

    float acc[TM][TN];
#pragma unroll
    for (int i = 0; i < TM; i++)
#pragma unroll
        for (int j = 0; j < TN; j++) acc[i][j] = 0.f;

    int a_row = tid >> 1;
    int a_col = (tid & 1) * 4;

    for (int k0 = 0; k0 < K; k0 += BK) {
        float4 av = *reinterpret_cast<const float4*>(&A[(size_t)(bm + a_row) * K + k0 + a_col]);
        As[a_col + 0][a_row] = av.x;
        As[a_col + 1][a_row] = av.y;
        As[a_col + 2][a_row] = av.z;
        As[a_col + 3][a_row] = av.w;

        float4 bv = *reinterpret_cast<const float4*>(&B[(size_t)(bn + a_row) * K + k0 + a_col]);
        Bs[a_col + 0][a_row] = bv.x;
        Bs[a_col + 1][a_row] = bv.y;
        Bs[a_col + 2][a_row] = bv.z;
        Bs[a_col + 3][a_row] = bv.w;
        __syncthreads();

#pragma unroll
        for (int kk = 0; kk < BK; kk++) {
            float ra[TM], rb[TN];
#pragma unroll
            for (int i = 0; i < TM; i++) ra[i] = As[kk][ty * TM + i];
#pragma unroll
            for (int j = 0; j < TN; j++) rb[j] = Bs[kk][tx * TN + j];
#pragma unroll
            for (int i = 0; i < TM; i++)
#pragma unroll
                for (int j = 0; j < TN; j++)
                    acc[i][j] = fmaf(ra[i], rb[j], acc[i][j]);
        }
        __syncthreads();
    }

#pragma unroll
    for (int i = 0; i < TM; i++) {
        int r = bm + ty * TM + i;
#pragma unroll
        for (int j = 0; j < TN; j++) {
            float s = 1.f / (1.f + expf(-acc[i][j]));
            C[(size_t)r * N + bn + tx * TN + j] = s;
        }
    }
}

// ---------------- CSR SpMM + bias (+relu): Y[r,:] = act(sum_e val[e]*X[col[e],:] + b) ----------------
__global__ void spmm_bias_kernel(const int* __restrict__ col, const float* __restrict__ val,
                                 const float* __restrict__ X, const float* __restrict__ bias,
                                 float* __restrict__ Y, int F, int do_relu)
{
    int r = blockIdx.x;
    int f = threadIdx.x;
    int e0 = g_rowptr[r];
    int e1 = g_rowptr[r + 1];
    float acc = 0.f;
    for (int e = e0; e < e1; e++) {
        int c = __ldg(&col[e]);          // uniform across block -> broadcast
        float w = __ldg(&val[e]);
        acc = fmaf(w, X[(size_t)c * F + f], acc);
    }
    float y = acc + bias[f];
    if (do_relu) y = fmaxf(y, 0.f);
    Y[(size_t)r * F + f] = y;
}

// ---------------- edge embedding: zu = z[u] @ We^T ; zv = z[v] ----------------
__global__ void edge_embed_kernel(const int* __restrict__ u, const int* __restrict__ v,
                                  const float* __restrict__ We)
{
    int b = blockIdx.x;
    int t = threadIdx.x;   // 0..127 = output class j
    __shared__ float zrow[NCLASS];
    zrow[t] = g_z[(size_t)u[b] * NCLASS + t];
    g_zv[(size_t)b * NCLASS + t] = g_z[(size_t)v[b] * NCLASS + t];
    __syncthreads();
    float acc = 0.f;
#pragma unroll 8
    for (int k = 0; k < NCLASS; k++)
        acc = fmaf(zrow[k], __ldg(&We[(size_t)t * NCLASS + k]), acc);
    g_zu[(size_t)b * NCLASS + t] = acc;
}

// ---------------- launch ----------------
extern "C" void kernel_launch(void* const* d_in, const int* in_sizes, int n_in,
                              void* d_out, int out_size)
{
    const int*   u       = (const int*)d_in[0];
    const int*   v       = (const int*)d_in[1];
    const float* x       = (const float*)d_in[2];
    const int*   adj_row = (const int*)d_in[3];
    const int*   adj_col = (const int*)d_in[4];
    const float* adj_val = (const float*)d_in[5];
    const float* W1      = (const float*)d_in[6];
    const float* b1      = (const float*)d_in[7];
    const float* W2      = (const float*)d_in[8];
    const float* b2      = (const float*)d_in[9];
    const float* We      = (const float*)d_in[10];
    float* out = (float*)d_out;

    float *support1, *h, *support2, *z, *zu, *zv;
    cudaGetSymbolAddress((void**)&support1, g_support1);
    cudaGetSymbolAddress((void**)&h,        g_h);
    cudaGetSymbolAddress((void**)&support2, g_support2);
    cudaGetSymbolAddress((void**)&z,        g_z);
    cudaGetSymbolAddress((void**)&zu,       g_zu);
    cudaGetSymbolAddress((void**)&zv,       g_zv);

    // 1. row pointers from sorted COO rows
    build_rowptr_kernel<<<(N_NODES + 1 + 255) / 256, 256>>>(adj_row);

    // 2. support1 = x @ W1      [50000x512 @ 512x256]
    {
        dim3 grid(NHID / 128, (N_NODES + 127) / 128);
        sgemm_nn_kernel<<<grid, 256>>>(x, W1, support1, N_NODES, NHID, NFEAT);
    }

    // 3. h = relu(A @ support1 + b1)
    spmm_bias_kernel<<<N_NODES, NHID>>>(adj_col, adj_val, support1, b1, h, NHID, 1);

    // 4. support2 = h @ W2      [50000x256 @ 256x128]
    {
        dim3 grid(NCLASS / 128, (N_NODES + 127) / 128);
        sgemm_nn_kernel<<<grid, 256>>>(h, W2, support2, N_NODES, NCLASS, NHID);
    }

    // 5. z = A @ support2 + b2
    spmm_bias_kernel<<<N_NODES, NCLASS>>>(adj_col, adj_val, support2, b2, z, NCLASS, 0);

    // 6. zu = z[u] @ We^T ; zv = z[v]
    edge_embed_kernel<<<N_UV, NCLASS>>>(u, v, We);

    // 7. out = sigmoid(zu @ zv^T)   [2048x2048x128]
    {
        dim3 grid(N_UV / 128, N_UV / 128);
        sgemm_nt_sigmoid_kernel<<<grid, 256>>>(zu, zv, out, N_UV, N_UV, NCLASS);
    }
}

// round 3
// speedup vs baseline: 1.5504x; 1.5504x over previous
#include <cuda_runtime.h>
#include <cuda_bf16.h>
#include <math.h>
#include <cstdint>

#define N_NODES 50000
#define N_EDGES 800000
#define NFEAT   512
#define NHID    256
#define NCLASS  128
#define N_UV    2048

// ---------------- scratch (device globals; no allocation allowed) ----------------
__device__ __nv_bfloat16 g_xhi[N_NODES * NFEAT];
__device__ __nv_bfloat16 g_xlo[N_NODES * NFEAT];
__device__ __nv_bfloat16 g_w1t_hi[NHID * NFEAT];
__device__ __nv_bfloat16 g_w1t_lo[NHID * NFEAT];
__device__ float         g_support1[N_NODES * NHID];
__device__ __nv_bfloat16 g_hhi[N_NODES * NHID];
__device__ __nv_bfloat16 g_hlo[N_NODES * NHID];
__device__ __nv_bfloat16 g_w2t_hi[NCLASS * NHID];
__device__ __nv_bfloat16 g_w2t_lo[NCLASS * NHID];
__device__ float         g_support2[N_NODES * NCLASS];
__device__ float         g_z[N_NODES * NCLASS];
__device__ __nv_bfloat16 g_zuhi[N_UV * NCLASS];
__device__ __nv_bfloat16 g_zulo[N_UV * NCLASS];
__device__ __nv_bfloat16 g_zvhi[N_UV * NCLASS];
__device__ __nv_bfloat16 g_zvlo[N_UV * NCLASS];
__device__ int           g_rowptr[N_NODES + 1];

// ---------------- helpers ----------------
__device__ __forceinline__ uint32_t smem_to_u32(const void* p) {
    uint32_t a;
    asm("{ .reg .u64 t; cvta.to.shared.u64 t, %1; cvt.u32.u64 %0, t; }" : "=r"(a) : "l"(p));
    return a;
}

__device__ __forceinline__ void ldsm_x4(uint32_t* r, uint32_t addr) {
    asm volatile("ldmatrix.sync.aligned.m8n8.x4.shared.b16 {%0,%1,%2,%3}, [%4];"
                 : "=r"(r[0]), "=r"(r[1]), "=r"(r[2]), "=r"(r[3]) : "r"(addr));
}

__device__ __forceinline__ void mma_bf16(float* d, const uint32_t* a, const uint32_t* b) {
    asm volatile(
        "mma.sync.aligned.m16n8k16.row.col.f32.bf16.bf16.f32 "
        "{%0,%1,%2,%3}, {%4,%5,%6,%7}, {%8,%9}, {%0,%1,%2,%3};\n"
        : "+f"(d[0]), "+f"(d[1]), "+f"(d[2]), "+f"(d[3])
        : "r"(a[0]), "r"(a[1]), "r"(a[2]), "r"(a[3]), "r"(b[0]), "r"(b[1]));
}

__device__ __forceinline__ void cp_async16(uint32_t dst, const void* src, int src_bytes) {
    asm volatile("cp.async.cg.shared.global [%0], [%1], 16, %2;"
                 :: "r"(dst), "l"(src), "r"(src_bytes) : "memory");
}
__device__ __forceinline__ void cp_commit() {
    asm volatile("cp.async.commit_group;" ::: "memory");
}
__device__ __forceinline__ void cp_wait1() {
    asm volatile("cp.async.wait_group 1;" ::: "memory");
}
__device__ __forceinline__ void cp_wait0() {
    asm volatile("cp.async.wait_group 0;" ::: "memory");
}

__device__ __forceinline__ void split_f32(float v, __nv_bfloat16& hi, __nv_bfloat16& lo) {
    hi = __float2bfloat16_rn(v);
    lo = __float2bfloat16_rn(v - __bfloat162float(hi));
}

// ---------------- row pointer build (adj_row is sorted) ----------------
__global__ void build_rowptr_kernel(const int* __restrict__ adj_row) {
    int i = blockIdx.x * blockDim.x + threadIdx.x;
    if (i > N_NODES) return;
    int lo = 0, hi = N_EDGES;
    while (lo < hi) {
        int mid = (lo + hi) >> 1;
        if (adj_row[mid] < i) lo = mid + 1; else hi = mid;
    }
    g_rowptr[i] = lo;
}

// ---------------- fp32 -> bf16 hi/lo split, vectorized ----------------
__global__ void split4_kernel(const float* __restrict__ src,
                              __nv_bfloat16* __restrict__ hi,
                              __nv_bfloat16* __restrict__ lo, int n4)
{
    int i = blockIdx.x * blockDim.x + threadIdx.x;
    if (i >= n4) return;
    float4 v = reinterpret_cast<const float4*>(src)[i];
    __nv_bfloat16 h0, h1, h2, h3, l0, l1, l2, l3;
    split_f32(v.x, h0, l0); split_f32(v.y, h1, l1);
    split_f32(v.z, h2, l2); split_f32(v.w, h3, l3);
    __nv_bfloat162* hp = reinterpret_cast<__nv_bfloat162*>(hi);
    __nv_bfloat162* lp = reinterpret_cast<__nv_bfloat162*>(lo);
    hp[i * 2 + 0] = __nv_bfloat162(h0, h1);
    hp[i * 2 + 1] = __nv_bfloat162(h2, h3);
    lp[i * 2 + 0] = __nv_bfloat162(l0, l1);
    lp[i * 2 + 1] = __nv_bfloat162(l2, l3);
}

// ---------------- W[K,N] -> Wt[N,K] + split (small) ----------------
__global__ void transpose_split_kernel(const float* __restrict__ in,
                                       __nv_bfloat16* __restrict__ hi,
                                       __nv_bfloat16* __restrict__ lo, int K, int N)
{
    int i = blockIdx.x * blockDim.x + threadIdx.x;
    if (i >= K * N) return;
    int k = i / N, n = i % N;
    __nv_bfloat16 h, l;
    split_f32(in[i], h, l);
    hi[(size_t)n * K + k] = h;
    lo[(size_t)n * K + k] = l;
}

// ---------------- HMMA GEMM: C[M,N] = act(A @ B^T), bf16x3 ----------------
// A (hi/lo): [M,K] K-major. B (hi/lo): [N,K] K-major. BM=BN=128, BK=64.
// 8 warps, each owns a 32x64 warp tile. Double-buffered cp.async pipeline.
// act: 0 = none, 1 = sigmoid.

#define GSTRIDE 144                    // smem row stride in bytes (72 bf16)
#define GTILE   (128 * GSTRIDE)        // 18432 bytes per operand tile
#define GBUF    (4 * GTILE)            // Ahi,Alo,Bhi,Blo = 73728 bytes

__global__ __launch_bounds__(256) void mma_gemm_kernel(
    const __nv_bfloat16* __restrict__ Ahi, const __nv_bfloat16* __restrict__ Alo,
    const __nv_bfloat16* __restrict__ Bhi, const __nv_bfloat16* __restrict__ Blo,
    float* __restrict__ C, int M, int N, int K, int act)
{
    extern __shared__ char smem_raw[];
    const uint32_t sb = smem_to_u32(smem_raw);

    const int tid  = threadIdx.x;
    const int wid  = tid >> 5;
    const int lane = tid & 31;
    const int warp_m = wid & 3;        // 4 warps along M
    const int warp_n = wid >> 2;       // 2 warps along N
    const int bm = blockIdx.y * 128;
    const int bn = blockIdx.x * 128;

    float acc[2][8][4];
#pragma unroll
    for (int mt = 0; mt < 2; mt++)
#pragma unroll
        for (int nt = 0; nt < 8; nt++)
#pragma unroll
            for (int i = 0; i < 4; i++) acc[mt][nt][i] = 0.f;

    const int NC = K >> 6;

    // -------- loader lambda (4 x 16B per thread per operand tile) --------
    auto load_chunk = [&](int c, uint32_t bufbase) {
        const int k0 = c << 6;
#pragma unroll
        for (int i = 0; i < 4; i++) {
            const int s = tid + i * 256;        // 0..1023
            const int row = s >> 3;
            const int seg = s & 7;
            const uint32_t soff = row * GSTRIDE + seg * 16;
            const int ar = bm + row;
            const int okA = (ar < M) ? 16 : 0;
            const int arc = okA ? ar : 0;
            const size_t aoff = (size_t)arc * K + k0 + seg * 8;
            cp_async16(bufbase + 0 * GTILE + soff, Ahi + aoff, okA);
            cp_async16(bufbase + 1 * GTILE + soff, Alo + aoff, okA);
            const size_t boff = (size_t)(bn + row) * K + k0 + seg * 8;
            cp_async16(bufbase + 2 * GTILE + soff, Bhi + boff, 16);
            cp_async16(bufbase + 3 * GTILE + soff, Blo + boff, 16);
        }
        cp_commit();
    };

    load_chunk(0, sb);

    for (int c = 0; c < NC; c++) {
        const uint32_t bufbase = sb + (c & 1) * GBUF;
        if (c + 1 < NC) {
            load_chunk(c + 1, sb + ((c + 1) & 1) * GBUF);
            cp_wait1();
        } else {
            cp_wait0();
        }
        __syncthreads();

        const uint32_t sA_hi = bufbase + 0 * GTILE;
        const uint32_t sA_lo = bufbase + 1 * GTILE;
        const uint32_t sB_hi = bufbase + 2 * GTILE;
        const uint32_t sB_lo = bufbase + 3 * GTILE;

#pragma unroll
        for (int ks = 0; ks < 4; ks++) {
            const int kc = ks * 16;
            uint32_t ah[2][4], al[2][4];
#pragma unroll
            for (int mt = 0; mt < 2; mt++) {
                const int row = warp_m * 32 + mt * 16 + (lane & 15);
                const int col = kc + ((lane >> 4) << 3);
                const uint32_t off = row * GSTRIDE + col * 2;
                ldsm_x4(ah[mt], sA_hi + off);
                ldsm_x4(al[mt], sA_lo + off);
            }
            uint32_t bh[8][2], bl[8][2];
#pragma unroll
            for (int bt = 0; bt < 4; bt++) {
                const int nrow = warp_n * 64 + bt * 16 + (lane & 7) + ((lane >> 4) & 1) * 8;
                const int col  = kc + ((lane >> 3) & 1) * 8;
                const uint32_t off = nrow * GSTRIDE + col * 2;
                uint32_t t[4];
                ldsm_x4(t, sB_hi + off);
                bh[bt * 2][0] = t[0]; bh[bt * 2][1] = t[1];
                bh[bt * 2 + 1][0] = t[2]; bh[bt * 2 + 1][1] = t[3];
                ldsm_x4(t, sB_lo + off);
                bl[bt * 2][0] = t[0]; bl[bt * 2][1] = t[1];
                bl[bt * 2 + 1][0] = t[2]; bl[bt * 2 + 1][1] = t[3];
            }
#pragma unroll
            for (int mt = 0; mt < 2; mt++)
#pragma unroll
                for (int nt = 0; nt < 8; nt++) {
                    mma_bf16(acc[mt][nt], ah[mt], bh[nt]);
                    mma_bf16(acc[mt][nt], ah[mt], bl[nt]);
                    mma_bf16(acc[mt][nt], al[mt], bh[nt]);
                }
        }
        __syncthreads();
    }

    // -------- epilogue --------
#pragma unroll
    for (int mt = 0; mt < 2; mt++) {
        const int row0 = bm + warp_m * 32 + mt * 16 + (lane >> 2);
#pragma unroll
        for (int h = 0; h < 2; h++) {
            const int row = row0 + h * 8;
            if (row >= M) continue;
            float* dst = C + (size_t)row * N + bn + warp_n * 64 + (lane & 3) * 2;
#pragma unroll
            for (int nt = 0; nt < 8; nt++) {
                float v0 = acc[mt][nt][h * 2 + 0];
                float v1 = acc[mt][nt][h * 2 + 1];
                if (act == 1) {
                    v0 = 1.f / (1.f + expf(-v0));
                    v1 = 1.f / (1.f + expf(-v1));
                }
                *reinterpret_cast<float2*>(dst + nt * 8) = make_float2(v0, v1);
            }
        }
    }
}

// ---------------- SpMM layer 1: h = relu(A @ support1 + b1), output split to bf16 ----------------
__global__ void spmm_relu_split_kernel(const int* __restrict__ col, const float* __restrict__ val,
                                       const float* __restrict__ X, const float* __restrict__ bias)
{
    int r = blockIdx.x;
    int f = threadIdx.x;          // 0..255
    int e0 = g_rowptr[r];
    int e1 = g_rowptr[r + 1];
    float acc = 0.f;
    for (int e = e0; e < e1; e++) {
        int c = __ldg(&col[e]);
        float w = __ldg(&val[e]);
        acc = fmaf(w, X[(size_t)c * NHID + f], acc);
    }
    float y = fmaxf(acc + bias[f], 0.f);
    __nv_bfloat16 h, l;
    split_f32(y, h, l);
    g_hhi[(size_t)r * NHID + f] = h;
    g_hlo[(size_t)r * NHID + f] = l;
}

// ---------------- SpMM layer 2: z = A @ support2 + b2 (fp32) ----------------
__global__ void spmm_plain_kernel(const int* __restrict__ col, const float* __restrict__ val,
                                  const float* __restrict__ X, const float* __restrict__ bias)
{
    int r = blockIdx.x;
    int f = threadIdx.x;          // 0..127
    int e0 = g_rowptr[r];
    int e1 = g_rowptr[r + 1];
    float acc = 0.f;
    for (int e = e0; e < e1; e++) {
        int c = __ldg(&col[e]);
        float w = __ldg(&val[e]);
        acc = fmaf(w, X[(size_t)c * NCLASS + f], acc);
    }
    g_z[(size_t)r * NCLASS + f] = acc + bias[f];
}

// ---------------- edge embedding: zu = z[u] @ We^T ; zv = z[v]; split both ----------------
__global__ void edge_embed_kernel(const int* __restrict__ u, const int* __restrict__ v,
                                  const float* __restrict__ We)
{
    int b = blockIdx.x;
    int t = threadIdx.x;          // 0..127
    __shared__ float zrow[NCLASS];
    zrow[t] = g_z[(size_t)u[b] * NCLASS + t];
    float zvv = g_z[(size_t)v[b] * NCLASS + t];
    __syncthreads();
    float acc = 0.f;
#pragma unroll 8
    for (int k = 0; k < NCLASS; k++)
        acc = fmaf(zrow[k], __ldg(&We[(size_t)t * NCLASS + k]), acc);
    __nv_bfloat16 h, l;
    split_f32(acc, h, l);
    g_zuhi[(size_t)b * NCLASS + t] = h;
    g_zulo[(size_t)b * NCLASS + t] = l;
    split_f32(zvv, h, l);
    g_zvhi[(size_t)b * NCLASS + t] = h;
    g_zvlo[(size_t)b * NCLASS + t] = l;
}

// ---------------- launch ----------------
extern "C" void kernel_launch(void* const* d_in, const int* in_sizes, int n_in,
                              void* d_out, int out_size)
{
    const int*   u       = (const int*)d_in[0];
    const int*   v       = (const int*)d_in[1];
    const float* x       = (const float*)d_in[2];
    const int*   adj_row = (const int*)d_in[3];
    const int*   adj_col = (const int*)d_in[4];
    const float* adj_val = (const float*)d_in[5];
    const float* W1      = (const float*)d_in[6];
    const float* b1      = (const float*)d_in[7];
    const float* W2      = (const float*)d_in[8];
    const float* b2      = (const float*)d_in[9];
    const float* We      = (const float*)d_in[10];
    float* out = (float*)d_out;

    __nv_bfloat16 *xhi, *xlo, *w1th, *w1tl, *hhi, *hlo, *w2th, *w2tl, *zuh, *zul, *zvh, *zvl;
    float *support1, *support2;
    cudaGetSymbolAddress((void**)&xhi, g_xhi);
    cudaGetSymbolAddress((void**)&xlo, g_xlo);
    cudaGetSymbolAddress((void**)&w1th, g_w1t_hi);
    cudaGetSymbolAddress((void**)&w1tl, g_w1t_lo);
    cudaGetSymbolAddress((void**)&support1, g_support1);
    cudaGetSymbolAddress((void**)&hhi, g_hhi);
    cudaGetSymbolAddress((void**)&hlo, g_hlo);
    cudaGetSymbolAddress((void**)&w2th, g_w2t_hi);
    cudaGetSymbolAddress((void**)&w2tl, g_w2t_lo);
    cudaGetSymbolAddress((void**)&support2, g_support2);
    cudaGetSymbolAddress((void**)&zuh, g_zuhi);
    cudaGetSymbolAddress((void**)&zul, g_zulo);
    cudaGetSymbolAddress((void**)&zvh, g_zvhi);
    cudaGetSymbolAddress((void**)&zvl, g_zvlo);

    const int SMEM_DYN = 2 * GBUF;   // 147456 bytes
    cudaFuncSetAttribute(mma_gemm_kernel, cudaFuncAttributeMaxDynamicSharedMemorySize, SMEM_DYN);

    // 1. row pointers from sorted COO rows
    build_rowptr_kernel<<<(N_NODES + 1 + 255) / 256, 256>>>(adj_row);

    // 2. split x -> bf16 hi/lo
    {
        int n4 = (N_NODES * NFEAT) / 4;
        split4_kernel<<<(n4 + 255) / 256, 256>>>(x, xhi, xlo, n4);
    }

    // 3. transpose+split weights
    transpose_split_kernel<<<(NFEAT * NHID + 255) / 256, 256>>>(W1, w1th, w1tl, NFEAT, NHID);
    transpose_split_kernel<<<(NHID * NCLASS + 255) / 256, 256>>>(W2, w2th, w2tl, NHID, NCLASS);

    // 4. support1 = x @ W1   (HMMA bf16x3)
    {
        dim3 grid(NHID / 128, (N_NODES + 127) / 128);
        mma_gemm_kernel<<<grid, 256, SMEM_DYN>>>(xhi, xlo, w1th, w1tl, support1,
                                                 N_NODES, NHID, NFEAT, 0);
    }

    // 5. h = relu(A @ support1 + b1), fused bf16 split
    spmm_relu_split_kernel<<<N_NODES, NHID>>>(adj_col, adj_val, support1, b1);

    // 6. support2 = h @ W2   (HMMA)
    {
        dim3 grid(NCLASS / 128, (N_NODES + 127) / 128);
        mma_gemm_kernel<<<grid, 256, SMEM_DYN>>>(hhi, hlo, w2th, w2tl, support2,
                                                 N_NODES, NCLASS, NHID, 0);
    }

    // 7. z = A @ support2 + b2
    spmm_plain_kernel<<<N_NODES, NCLASS>>>(adj_col, adj_val, support2, b2);

    // 8. zu = z[u] @ We^T ; zv = z[v] ; split to bf16
    edge_embed_kernel<<<N_UV, NCLASS>>>(u, v, We);

    // 9. out = sigmoid(zu @ zv^T)  (HMMA, fused sigmoid)
    {
        dim3 grid(N_UV / 128, N_UV / 128);
        mma_gemm_kernel<<<grid, 256, SMEM_DYN>>>(zuh, zul, zvh, zvl, out,
                                                 N_UV, N_UV, NCLASS, 1);
    }
}

// round 4
// speedup vs baseline: 1.8561x; 1.1972x over previous
#include <cuda_runtime.h>
#include <cuda_bf16.h>
#include <math.h>
#include <cstdint>

#define N_NODES 50000
#define N_EDGES 800000
#define NFEAT   512
#define NHID    256
#define NCLASS  128
#define N_UV    2048

// ---------------- scratch (device globals; no allocation allowed) ----------------
__device__ __nv_bfloat16 g_xhi[N_NODES * NFEAT];
__device__ __nv_bfloat16 g_xlo[N_NODES * NFEAT];
__device__ __nv_bfloat16 g_w1t_hi[NHID * NFEAT];
__device__ __nv_bfloat16 g_w1t_lo[NHID * NFEAT];
__device__ float         g_support1[N_NODES * NHID];
__device__ __nv_bfloat16 g_hhi[N_NODES * NHID];
__device__ __nv_bfloat16 g_hlo[N_NODES * NHID];
__device__ __nv_bfloat16 g_w2t_hi[NCLASS * NHID];
__device__ __nv_bfloat16 g_w2t_lo[NCLASS * NHID];
__device__ float         g_support2[N_NODES * NCLASS];
__device__ float         g_z[N_NODES * NCLASS];
__device__ __nv_bfloat16 g_zuhi[N_UV * NCLASS];
__device__ __nv_bfloat16 g_zulo[N_UV * NCLASS];
__device__ __nv_bfloat16 g_zvhi[N_UV * NCLASS];
__device__ __nv_bfloat16 g_zvlo[N_UV * NCLASS];
__device__ int           g_rowptr[N_NODES + 1];

// ---------------- helpers ----------------
__device__ __forceinline__ uint32_t smem_to_u32(const void* p) {
    uint32_t a;
    asm("{ .reg .u64 t; cvta.to.shared.u64 t, %1; cvt.u32.u64 %0, t; }" : "=r"(a) : "l"(p));
    return a;
}

__device__ __forceinline__ void ldsm_x4(uint32_t* r, uint32_t addr) {
    asm volatile("ldmatrix.sync.aligned.m8n8.x4.shared.b16 {%0,%1,%2,%3}, [%4];"
                 : "=r"(r[0]), "=r"(r[1]), "=r"(r[2]), "=r"(r[3]) : "r"(addr));
}

__device__ __forceinline__ void mma_bf16(float* d, const uint32_t* a, const uint32_t* b) {
    asm volatile(
        "mma.sync.aligned.m16n8k16.row.col.f32.bf16.bf16.f32 "
        "{%0,%1,%2,%3}, {%4,%5,%6,%7}, {%8,%9}, {%0,%1,%2,%3};\n"
        : "+f"(d[0]), "+f"(d[1]), "+f"(d[2]), "+f"(d[3])
        : "r"(a[0]), "r"(a[1]), "r"(a[2]), "r"(a[3]), "r"(b[0]), "r"(b[1]));
}

__device__ __forceinline__ void cp_async16(uint32_t dst, const void* src, int src_bytes) {
    asm volatile("cp.async.cg.shared.global [%0], [%1], 16, %2;"
                 :: "r"(dst), "l"(src), "r"(src_bytes) : "memory");
}
__device__ __forceinline__ void cp_commit() {
    asm volatile("cp.async.commit_group;" ::: "memory");
}
__device__ __forceinline__ void cp_wait1() {
    asm volatile("cp.async.wait_group 1;" ::: "memory");
}
__device__ __forceinline__ void cp_wait0() {
    asm volatile("cp.async.wait_group 0;" ::: "memory");
}

__device__ __forceinline__ void split_f32(float v, __nv_bfloat16& hi, __nv_bfloat16& lo) {
    hi = __float2bfloat16_rn(v);
    lo = __float2bfloat16_rn(v - __bfloat162float(hi));
}

// ---------------- row pointer build (adj_row is sorted) ----------------
__global__ void build_rowptr_kernel(const int* __restrict__ adj_row) {
    int i = blockIdx.x * blockDim.x + threadIdx.x;
    if (i > N_NODES) return;
    int lo = 0, hi = N_EDGES;
    while (lo < hi) {
        int mid = (lo + hi) >> 1;
        if (adj_row[mid] < i) lo = mid + 1; else hi = mid;
    }
    g_rowptr[i] = lo;
}

// ---------------- fp32 -> bf16 hi/lo split, vectorized ----------------
__global__ void split4_kernel(const float* __restrict__ src,
                              __nv_bfloat16* __restrict__ hi,
                              __nv_bfloat16* __restrict__ lo, int n4)
{
    int i = blockIdx.x * blockDim.x + threadIdx.x;
    if (i >= n4) return;
    float4 v = reinterpret_cast<const float4*>(src)[i];
    __nv_bfloat16 h0, h1, h2, h3, l0, l1, l2, l3;
    split_f32(v.x, h0, l0); split_f32(v.y, h1, l1);
    split_f32(v.z, h2, l2); split_f32(v.w, h3, l3);
    __nv_bfloat162* hp = reinterpret_cast<__nv_bfloat162*>(hi);
    __nv_bfloat162* lp = reinterpret_cast<__nv_bfloat162*>(lo);
    hp[i * 2 + 0] = __nv_bfloat162(h0, h1);
    hp[i * 2 + 1] = __nv_bfloat162(h2, h3);
    lp[i * 2 + 0] = __nv_bfloat162(l0, l1);
    lp[i * 2 + 1] = __nv_bfloat162(l2, l3);
}

// ---------------- W[K,N] -> Wt[N,K] + split (small) ----------------
__global__ void transpose_split_kernel(const float* __restrict__ in,
                                       __nv_bfloat16* __restrict__ hi,
                                       __nv_bfloat16* __restrict__ lo, int K, int N)
{
    int i = blockIdx.x * blockDim.x + threadIdx.x;
    if (i >= K * N) return;
    int k = i / N, n = i % N;
    __nv_bfloat16 h, l;
    split_f32(in[i], h, l);
    hi[(size_t)n * K + k] = h;
    lo[(size_t)n * K + k] = l;
}

// ---------------- HMMA GEMM: C[M,N] = act(A @ B^T), bf16x3 ----------------
#define GSTRIDE 144                    // smem row stride in bytes (72 bf16)
#define GTILE   (128 * GSTRIDE)        // 18432 bytes per operand tile
#define GBUF    (4 * GTILE)            // Ahi,Alo,Bhi,Blo = 73728 bytes

__global__ __launch_bounds__(256) void mma_gemm_kernel(
    const __nv_bfloat16* __restrict__ Ahi, const __nv_bfloat16* __restrict__ Alo,
    const __nv_bfloat16* __restrict__ Bhi, const __nv_bfloat16* __restrict__ Blo,
    float* __restrict__ C, int M, int N, int K, int act)
{
    extern __shared__ char smem_raw[];
    const uint32_t sb = smem_to_u32(smem_raw);

    const int tid  = threadIdx.x;
    const int wid  = tid >> 5;
    const int lane = tid & 31;
    const int warp_m = wid & 3;        // 4 warps along M
    const int warp_n = wid >> 2;       // 2 warps along N
    const int bm = blockIdx.y * 128;
    const int bn = blockIdx.x * 128;

    float acc[2][8][4];
#pragma unroll
    for (int mt = 0; mt < 2; mt++)
#pragma unroll
        for (int nt = 0; nt < 8; nt++)
#pragma unroll
            for (int i = 0; i < 4; i++) acc[mt][nt][i] = 0.f;

    const int NC = K >> 6;

    auto load_chunk = [&](int c, uint32_t bufbase) {
        const int k0 = c << 6;
#pragma unroll
        for (int i = 0; i < 4; i++) {
            const int s = tid + i * 256;        // 0..1023
            const int row = s >> 3;
            const int seg = s & 7;
            const uint32_t soff = row * GSTRIDE + seg * 16;
            const int ar = bm + row;
            const int okA = (ar < M) ? 16 : 0;
            const int arc = okA ? ar : 0;
            const size_t aoff = (size_t)arc * K + k0 + seg * 8;
            cp_async16(bufbase + 0 * GTILE + soff, Ahi + aoff, okA);
            cp_async16(bufbase + 1 * GTILE + soff, Alo + aoff, okA);
            const size_t boff = (size_t)(bn + row) * K + k0 + seg * 8;
            cp_async16(bufbase + 2 * GTILE + soff, Bhi + boff, 16);
            cp_async16(bufbase + 3 * GTILE + soff, Blo + boff, 16);
        }
        cp_commit();
    };

    load_chunk(0, sb);

    for (int c = 0; c < NC; c++) {
        const uint32_t bufbase = sb + (c & 1) * GBUF;
        if (c + 1 < NC) {
            load_chunk(c + 1, sb + ((c + 1) & 1) * GBUF);
            cp_wait1();
        } else {
            cp_wait0();
        }
        __syncthreads();

        const uint32_t sA_hi = bufbase + 0 * GTILE;
        const uint32_t sA_lo = bufbase + 1 * GTILE;
        const uint32_t sB_hi = bufbase + 2 * GTILE;
        const uint32_t sB_lo = bufbase + 3 * GTILE;

#pragma unroll
        for (int ks = 0; ks < 4; ks++) {
            const int kc = ks * 16;
            uint32_t ah[2][4], al[2][4];
#pragma unroll
            for (int mt = 0; mt < 2; mt++) {
                const int row = warp_m * 32 + mt * 16 + (lane & 15);
                const int col = kc + ((lane >> 4) << 3);
                const uint32_t off = row * GSTRIDE + col * 2;
                ldsm_x4(ah[mt], sA_hi + off);
                ldsm_x4(al[mt], sA_lo + off);
            }
            uint32_t bh[8][2], bl[8][2];
#pragma unroll
            for (int bt = 0; bt < 4; bt++) {
                const int nrow = warp_n * 64 + bt * 16 + (lane & 7) + ((lane >> 4) & 1) * 8;
                const int col  = kc + ((lane >> 3) & 1) * 8;
                const uint32_t off = nrow * GSTRIDE + col * 2;
                uint32_t t[4];
                ldsm_x4(t, sB_hi + off);
                bh[bt * 2][0] = t[0]; bh[bt * 2][1] = t[1];
                bh[bt * 2 + 1][0] = t[2]; bh[bt * 2 + 1][1] = t[3];
                ldsm_x4(t, sB_lo + off);
                bl[bt * 2][0] = t[0]; bl[bt * 2][1] = t[1];
                bl[bt * 2 + 1][0] = t[2]; bl[bt * 2 + 1][1] = t[3];
            }
#pragma unroll
            for (int mt = 0; mt < 2; mt++)
#pragma unroll
                for (int nt = 0; nt < 8; nt++) {
                    mma_bf16(acc[mt][nt], ah[mt], bh[nt]);
                    mma_bf16(acc[mt][nt], ah[mt], bl[nt]);
                    mma_bf16(acc[mt][nt], al[mt], bh[nt]);
                }
        }
        __syncthreads();
    }

    // -------- epilogue --------
#pragma unroll
    for (int mt = 0; mt < 2; mt++) {
        const int row0 = bm + warp_m * 32 + mt * 16 + (lane >> 2);
#pragma unroll
        for (int h = 0; h < 2; h++) {
            const int row = row0 + h * 8;
            if (row >= M) continue;
            float* dst = C + (size_t)row * N + bn + warp_n * 64 + (lane & 3) * 2;
#pragma unroll
            for (int nt = 0; nt < 8; nt++) {
                float v0 = acc[mt][nt][h * 2 + 0];
                float v1 = acc[mt][nt][h * 2 + 1];
                if (act == 1) {
                    v0 = 1.f / (1.f + expf(-v0));
                    v1 = 1.f / (1.f + expf(-v1));
                }
                *reinterpret_cast<float2*>(dst + nt * 8) = make_float2(v0, v1);
            }
        }
    }
}

// ---------------- SpMM layer 1: h = relu(A @ support1 + b1), split to bf16 ----------------
// float4 gather: 64 lanes per row, 4 rows per 256-thread block. 50000/4 = 12500 blocks.
__global__ __launch_bounds__(256) void spmm_relu_split_kernel(
    const int* __restrict__ col, const float* __restrict__ val,
    const float* __restrict__ X, const float* __restrict__ bias)
{
    const int r  = blockIdx.x * 4 + (threadIdx.x >> 6);
    const int f4 = threadIdx.x & 63;                 // float4 index within row
    const float4* __restrict__ X4 = reinterpret_cast<const float4*>(X);

    const int e0 = g_rowptr[r];
    const int e1 = g_rowptr[r + 1];

    float4 a0 = make_float4(0.f, 0.f, 0.f, 0.f);
    float4 a1 = make_float4(0.f, 0.f, 0.f, 0.f);
    int e = e0;
    for (; e + 2 <= e1; e += 2) {
        const int   c0 = __ldg(&col[e]);
        const int   c1 = __ldg(&col[e + 1]);
        const float w0 = __ldg(&val[e]);
        const float w1 = __ldg(&val[e + 1]);
        const float4 v0 = X4[(size_t)c0 * 64 + f4];
        const float4 v1 = X4[(size_t)c1 * 64 + f4];
        a0.x = fmaf(w0, v0.x, a0.x); a0.y = fmaf(w0, v0.y, a0.y);
        a0.z = fmaf(w0, v0.z, a0.z); a0.w = fmaf(w0, v0.w, a0.w);
        a1.x = fmaf(w1, v1.x, a1.x); a1.y = fmaf(w1, v1.y, a1.y);
        a1.z = fmaf(w1, v1.z, a1.z); a1.w = fmaf(w1, v1.w, a1.w);
    }
    if (e < e1) {
        const int   c0 = __ldg(&col[e]);
        const float w0 = __ldg(&val[e]);
        const float4 v0 = X4[(size_t)c0 * 64 + f4];
        a0.x = fmaf(w0, v0.x, a0.x); a0.y = fmaf(w0, v0.y, a0.y);
        a0.z = fmaf(w0, v0.z, a0.z); a0.w = fmaf(w0, v0.w, a0.w);
    }
    const float4 b = reinterpret_cast<const float4*>(bias)[f4];
    float y0 = fmaxf(a0.x + a1.x + b.x, 0.f);
    float y1 = fmaxf(a0.y + a1.y + b.y, 0.f);
    float y2 = fmaxf(a0.z + a1.z + b.z, 0.f);
    float y3 = fmaxf(a0.w + a1.w + b.w, 0.f);

    __nv_bfloat16 h0, h1, h2, h3, l0, l1, l2, l3;
    split_f32(y0, h0, l0); split_f32(y1, h1, l1);
    split_f32(y2, h2, l2); split_f32(y3, h3, l3);
    __nv_bfloat162* hp = reinterpret_cast<__nv_bfloat162*>(g_hhi);
    __nv_bfloat162* lp = reinterpret_cast<__nv_bfloat162*>(g_hlo);
    const size_t o2 = (size_t)r * (NHID / 2) + f4 * 2;
    hp[o2 + 0] = __nv_bfloat162(h0, h1);
    hp[o2 + 1] = __nv_bfloat162(h2, h3);
    lp[o2 + 0] = __nv_bfloat162(l0, l1);
    lp[o2 + 1] = __nv_bfloat162(l2, l3);
}

// ---------------- SpMM layer 2: z = A @ support2 + b2 (fp32) ----------------
// float4 gather: 32 lanes per row, 8 rows per 256-thread block. 50000/8 = 6250 blocks.
__global__ __launch_bounds__(256) void spmm_plain_kernel(
    const int* __restrict__ col, const float* __restrict__ val,
    const float* __restrict__ X, const float* __restrict__ bias)
{
    const int r  = blockIdx.x * 8 + (threadIdx.x >> 5);
    const int f4 = threadIdx.x & 31;
    const float4* __restrict__ X4 = reinterpret_cast<const float4*>(X);

    const int e0 = g_rowptr[r];
    const int e1 = g_rowptr[r + 1];

    float4 a0 = make_float4(0.f, 0.f, 0.f, 0.f);
    float4 a1 = make_float4(0.f, 0.f, 0.f, 0.f);
    int e = e0;
    for (; e + 2 <= e1; e += 2) {
        const int   c0 = __ldg(&col[e]);
        const int   c1 = __ldg(&col[e + 1]);
        const float w0 = __ldg(&val[e]);
        const float w1 = __ldg(&val[e + 1]);
        const float4 v0 = X4[(size_t)c0 * 32 + f4];
        const float4 v1 = X4[(size_t)c1 * 32 + f4];
        a0.x = fmaf(w0, v0.x, a0.x); a0.y = fmaf(w0, v0.y, a0.y);
        a0.z = fmaf(w0, v0.z, a0.z); a0.w = fmaf(w0, v0.w, a0.w);
        a1.x = fmaf(w1, v1.x, a1.x); a1.y = fmaf(w1, v1.y, a1.y);
        a1.z = fmaf(w1, v1.z, a1.z); a1.w = fmaf(w1, v1.w, a1.w);
    }
    if (e < e1) {
        const int   c0 = __ldg(&col[e]);
        const float w0 = __ldg(&val[e]);
        const float4 v0 = X4[(size_t)c0 * 32 + f4];
        a0.x = fmaf(w0, v0.x, a0.x); a0.y = fmaf(w0, v0.y, a0.y);
        a0.z = fmaf(w0, v0.z, a0.z); a0.w = fmaf(w0, v0.w, a0.w);
    }
    const float4 b = reinterpret_cast<const float4*>(bias)[f4];
    float4 out;
    out.x = a0.x + a1.x + b.x;
    out.y = a0.y + a1.y + b.y;
    out.z = a0.z + a1.z + b.z;
    out.w = a0.w + a1.w + b.w;
    reinterpret_cast<float4*>(g_z)[(size_t)r * 32 + f4] = out;
}

// ---------------- edge embedding: zu = z[u] @ We^T ; zv = z[v]; split both ----------------
__global__ void edge_embed_kernel(const int* __restrict__ u, const int* __restrict__ v,
                                  const float* __restrict__ We)
{
    int b = blockIdx.x;
    int t = threadIdx.x;          // 0..127
    __shared__ float zrow[NCLASS];
    zrow[t] = g_z[(size_t)u[b] * NCLASS + t];
    float zvv = g_z[(size_t)v[b] * NCLASS + t];
    __syncthreads();
    float acc = 0.f;
#pragma unroll 8
    for (int k = 0; k < NCLASS; k++)
        acc = fmaf(zrow[k], __ldg(&We[(size_t)t * NCLASS + k]), acc);
    __nv_bfloat16 h, l;
    split_f32(acc, h, l);
    g_zuhi[(size_t)b * NCLASS + t] = h;
    g_zulo[(size_t)b * NCLASS + t] = l;
    split_f32(zvv, h, l);
    g_zvhi[(size_t)b * NCLASS + t] = h;
    g_zvlo[(size_t)b * NCLASS + t] = l;
}

// ---------------- launch ----------------
extern "C" void kernel_launch(void* const* d_in, const int* in_sizes, int n_in,
                              void* d_out, int out_size)
{
    const int*   u       = (const int*)d_in[0];
    const int*   v       = (const int*)d_in[1];
    const float* x       = (const float*)d_in[2];
    const int*   adj_row = (const int*)d_in[3];
    const int*   adj_col = (const int*)d_in[4];
    const float* adj_val = (const float*)d_in[5];
    const float* W1      = (const float*)d_in[6];
    const float* b1      = (const float*)d_in[7];
    const float* W2      = (const float*)d_in[8];
    const float* b2      = (const float*)d_in[9];
    const float* We      = (const float*)d_in[10];
    float* out = (float*)d_out;

    __nv_bfloat16 *xhi, *xlo, *w1th, *w1tl, *hhi, *hlo, *w2th, *w2tl, *zuh, *zul, *zvh, *zvl;
    float *support1, *support2;
    cudaGetSymbolAddress((void**)&xhi, g_xhi);
    cudaGetSymbolAddress((void**)&xlo, g_xlo);
    cudaGetSymbolAddress((void**)&w1th, g_w1t_hi);
    cudaGetSymbolAddress((void**)&w1tl, g_w1t_lo);
    cudaGetSymbolAddress((void**)&support1, g_support1);
    cudaGetSymbolAddress((void**)&hhi, g_hhi);
    cudaGetSymbolAddress((void**)&hlo, g_hlo);
    cudaGetSymbolAddress((void**)&w2th, g_w2t_hi);
    cudaGetSymbolAddress((void**)&w2tl, g_w2t_lo);
    cudaGetSymbolAddress((void**)&support2, g_support2);
    cudaGetSymbolAddress((void**)&zuh, g_zuhi);
    cudaGetSymbolAddress((void**)&zul, g_zulo);
    cudaGetSymbolAddress((void**)&zvh, g_zvhi);
    cudaGetSymbolAddress((void**)&zvl, g_zvlo);

    const int SMEM_DYN = 2 * GBUF;   // 147456 bytes
    cudaFuncSetAttribute(mma_gemm_kernel, cudaFuncAttributeMaxDynamicSharedMemorySize, SMEM_DYN);

    // 1. row pointers from sorted COO rows
    build_rowptr_kernel<<<(N_NODES + 1 + 255) / 256, 256>>>(adj_row);

    // 2. split x -> bf16 hi/lo
    {
        int n4 = (N_NODES * NFEAT) / 4;
        split4_kernel<<<(n4 + 255) / 256, 256>>>(x, xhi, xlo, n4);
    }

    // 3. transpose+split weights
    transpose_split_kernel<<<(NFEAT * NHID + 255) / 256, 256>>>(W1, w1th, w1tl, NFEAT, NHID);
    transpose_split_kernel<<<(NHID * NCLASS + 255) / 256, 256>>>(W2, w2th, w2tl, NHID, NCLASS);

    // 4. support1 = x @ W1   (HMMA bf16x3)
    {
        dim3 grid(NHID / 128, (N_NODES + 127) / 128);
        mma_gemm_kernel<<<grid, 256, SMEM_DYN>>>(xhi, xlo, w1th, w1tl, support1,
                                                 N_NODES, NHID, NFEAT, 0);
    }

    // 5. h = relu(A @ support1 + b1), fused bf16 split
    spmm_relu_split_kernel<<<N_NODES / 4, 256>>>(adj_col, adj_val, support1, b1);

    // 6. support2 = h @ W2   (HMMA)
    {
        dim3 grid(NCLASS / 128, (N_NODES + 127) / 128);
        mma_gemm_kernel<<<grid, 256, SMEM_DYN>>>(hhi, hlo, w2th, w2tl, support2,
                                                 N_NODES, NCLASS, NHID, 0);
    }

    // 7. z = A @ support2 + b2
    spmm_plain_kernel<<<N_NODES / 8, 256>>>(adj_col, adj_val, support2, b2);

    // 8. zu = z[u] @ We^T ; zv = z[v] ; split to bf16
    edge_embed_kernel<<<N_UV, NCLASS>>>(u, v, We);

    // 9. out = sigmoid(zu @ zv^T)  (HMMA, fused sigmoid)
    {
        dim3 grid(N_UV / 128, N_UV / 128);
        mma_gemm_kernel<<<grid, 256, SMEM_DYN>>>(zuh, zul, zvh, zvl, out,
                                                 N_UV, N_UV, NCLASS, 1);
    }
}

// round 5
// speedup vs baseline: 1.8719x; 1.0085x over previous
#include <cuda_runtime.h>
#include <cuda_bf16.h>
#include <math.h>
#include <cstdint>

#define N_NODES 50000
#define N_EDGES 800000
#define NFEAT   512
#define NHID    256
#define NCLASS  128
#define N_UV    2048

// ---------------- scratch (device globals; no allocation allowed) ----------------
__device__ __nv_bfloat16 g_xhi[N_NODES * NFEAT];
__device__ __nv_bfloat16 g_xlo[N_NODES * NFEAT];
__device__ __nv_bfloat16 g_w1t_hi[NHID * NFEAT];
__device__ __nv_bfloat16 g_w1t_lo[NHID * NFEAT];
__device__ float         g_support1[N_NODES * NHID];
__device__ __nv_bfloat16 g_hhi[N_NODES * NHID];
__device__ __nv_bfloat16 g_hlo[N_NODES * NHID];
__device__ __nv_bfloat16 g_w2t_hi[NCLASS * NHID];
__device__ __nv_bfloat16 g_w2t_lo[NCLASS * NHID];
__device__ float         g_support2[N_NODES * NCLASS];
__device__ __nv_bfloat16 g_zuhi[N_UV * NCLASS];
__device__ __nv_bfloat16 g_zulo[N_UV * NCLASS];
__device__ __nv_bfloat16 g_zvhi[N_UV * NCLASS];
__device__ __nv_bfloat16 g_zvlo[N_UV * NCLASS];
__device__ int           g_rowptr[N_NODES + 1];

// ---------------- helpers ----------------
__device__ __forceinline__ uint32_t smem_to_u32(const void* p) {
    uint32_t a;
    asm("{ .reg .u64 t; cvta.to.shared.u64 t, %1; cvt.u32.u64 %0, t; }" : "=r"(a) : "l"(p));
    return a;
}

__device__ __forceinline__ void ldsm_x4(uint32_t* r, uint32_t addr) {
    asm volatile("ldmatrix.sync.aligned.m8n8.x4.shared.b16 {%0,%1,%2,%3}, [%4];"
                 : "=r"(r[0]), "=r"(r[1]), "=r"(r[2]), "=r"(r[3]) : "r"(addr));
}

__device__ __forceinline__ void mma_bf16(float* d, const uint32_t* a, const uint32_t* b) {
    asm volatile(
        "mma.sync.aligned.m16n8k16.row.col.f32.bf16.bf16.f32 "
        "{%0,%1,%2,%3}, {%4,%5,%6,%7}, {%8,%9}, {%0,%1,%2,%3};\n"
        : "+f"(d[0]), "+f"(d[1]), "+f"(d[2]), "+f"(d[3])
        : "r"(a[0]), "r"(a[1]), "r"(a[2]), "r"(a[3]), "r"(b[0]), "r"(b[1]));
}

__device__ __forceinline__ void cp_async16(uint32_t dst, const void* src, int src_bytes) {
    asm volatile("cp.async.cg.shared.global [%0], [%1], 16, %2;"
                 :: "r"(dst), "l"(src), "r"(src_bytes) : "memory");
}
__device__ __forceinline__ void cp_commit() {
    asm volatile("cp.async.commit_group;" ::: "memory");
}
__device__ __forceinline__ void cp_wait1() {
    asm volatile("cp.async.wait_group 1;" ::: "memory");
}
__device__ __forceinline__ void cp_wait0() {
    asm volatile("cp.async.wait_group 0;" ::: "memory");
}

__device__ __forceinline__ void split_f32(float v, __nv_bfloat16& hi, __nv_bfloat16& lo) {
    hi = __float2bfloat16_rn(v);
    lo = __float2bfloat16_rn(v - __bfloat162float(hi));
}

// ---------------- row pointer build (adj_row is sorted) ----------------
__global__ void build_rowptr_kernel(const int* __restrict__ adj_row) {
    int i = blockIdx.x * blockDim.x + threadIdx.x;
    if (i > N_NODES) return;
    int lo = 0, hi = N_EDGES;
    while (lo < hi) {
        int mid = (lo + hi) >> 1;
        if (adj_row[mid] < i) lo = mid + 1; else hi = mid;
    }
    g_rowptr[i] = lo;
}

// ---------------- fp32 -> bf16 hi/lo split, vectorized ----------------
__global__ void split4_kernel(const float* __restrict__ src,
                              __nv_bfloat16* __restrict__ hi,
                              __nv_bfloat16* __restrict__ lo, int n4)
{
    int i = blockIdx.x * blockDim.x + threadIdx.x;
    if (i >= n4) return;
    float4 v = reinterpret_cast<const float4*>(src)[i];
    __nv_bfloat16 h0, h1, h2, h3, l0, l1, l2, l3;
    split_f32(v.x, h0, l0); split_f32(v.y, h1, l1);
    split_f32(v.z, h2, l2); split_f32(v.w, h3, l3);
    __nv_bfloat162* hp = reinterpret_cast<__nv_bfloat162*>(hi);
    __nv_bfloat162* lp = reinterpret_cast<__nv_bfloat162*>(lo);
    hp[i * 2 + 0] = __nv_bfloat162(h0, h1);
    hp[i * 2 + 1] = __nv_bfloat162(h2, h3);
    lp[i * 2 + 0] = __nv_bfloat162(l0, l1);
    lp[i * 2 + 1] = __nv_bfloat162(l2, l3);
}

// ---------------- W1[K,N]->W1t + W2[K,N]->W2t, both split, single launch ----------------
__global__ void prep_weights_kernel(const float* __restrict__ W1, const float* __restrict__ W2)
{
    int i = blockIdx.x * blockDim.x + threadIdx.x;
    if (i < NFEAT * NHID) {
        int k = i / NHID, n = i % NHID;
        __nv_bfloat16 h, l;
        split_f32(W1[i], h, l);
        g_w1t_hi[(size_t)n * NFEAT + k] = h;
        g_w1t_lo[(size_t)n * NFEAT + k] = l;
    } else {
        int j = i - NFEAT * NHID;
        if (j < NHID * NCLASS) {
            int k = j / NCLASS, n = j % NCLASS;
            __nv_bfloat16 h, l;
            split_f32(W2[j], h, l);
            g_w2t_hi[(size_t)n * NHID + k] = h;
            g_w2t_lo[(size_t)n * NHID + k] = l;
        }
    }
}

// ---------------- HMMA GEMM: C[M,N] = act(A @ B^T), bf16x3 ----------------
#define GSTRIDE 144                    // smem row stride in bytes (72 bf16)
#define GTILE   (128 * GSTRIDE)        // 18432 bytes per operand tile
#define GBUF    (4 * GTILE)            // Ahi,Alo,Bhi,Blo = 73728 bytes

__global__ __launch_bounds__(256) void mma_gemm_kernel(
    const __nv_bfloat16* __restrict__ Ahi, const __nv_bfloat16* __restrict__ Alo,
    const __nv_bfloat16* __restrict__ Bhi, const __nv_bfloat16* __restrict__ Blo,
    float* __restrict__ C, int M, int N, int K, int act)
{
    extern __shared__ char smem_raw[];
    const uint32_t sb = smem_to_u32(smem_raw);

    const int tid  = threadIdx.x;
    const int wid  = tid >> 5;
    const int lane = tid & 31;
    const int warp_m = wid & 3;        // 4 warps along M
    const int warp_n = wid >> 2;       // 2 warps along N
    const int bm = blockIdx.y * 128;
    const int bn = blockIdx.x * 128;

    float acc[2][8][4];
#pragma unroll
    for (int mt = 0; mt < 2; mt++)
#pragma unroll
        for (int nt = 0; nt < 8; nt++)
#pragma unroll
            for (int i = 0; i < 4; i++) acc[mt][nt][i] = 0.f;

    const int NC = K >> 6;

    auto load_chunk = [&](int c, uint32_t bufbase) {
        const int k0 = c << 6;
#pragma unroll
        for (int i = 0; i < 4; i++) {
            const int s = tid + i * 256;        // 0..1023
            const int row = s >> 3;
            const int seg = s & 7;
            const uint32_t soff = row * GSTRIDE + seg * 16;
            const int ar = bm + row;
            const int okA = (ar < M) ? 16 : 0;
            const int arc = okA ? ar : 0;
            const size_t aoff = (size_t)arc * K + k0 + seg * 8;
            cp_async16(bufbase + 0 * GTILE + soff, Ahi + aoff, okA);
            cp_async16(bufbase + 1 * GTILE + soff, Alo + aoff, okA);
            const size_t boff = (size_t)(bn + row) * K + k0 + seg * 8;
            cp_async16(bufbase + 2 * GTILE + soff, Bhi + boff, 16);
            cp_async16(bufbase + 3 * GTILE + soff, Blo + boff, 16);
        }
        cp_commit();
    };

    load_chunk(0, sb);

    for (int c = 0; c < NC; c++) {
        const uint32_t bufbase = sb + (c & 1) * GBUF;
        if (c + 1 < NC) {
            load_chunk(c + 1, sb + ((c + 1) & 1) * GBUF);
            cp_wait1();
        } else {
            cp_wait0();
        }
        __syncthreads();

        const uint32_t sA_hi = bufbase + 0 * GTILE;
        const uint32_t sA_lo = bufbase + 1 * GTILE;
        const uint32_t sB_hi = bufbase + 2 * GTILE;
        const uint32_t sB_lo = bufbase + 3 * GTILE;

#pragma unroll
        for (int ks = 0; ks < 4; ks++) {
            const int kc = ks * 16;
            uint32_t ah[2][4], al[2][4];
#pragma unroll
            for (int mt = 0; mt < 2; mt++) {
                const int row = warp_m * 32 + mt * 16 + (lane & 15);
                const int col = kc + ((lane >> 4) << 3);
                const uint32_t off = row * GSTRIDE + col * 2;
                ldsm_x4(ah[mt], sA_hi + off);
                ldsm_x4(al[mt], sA_lo + off);
            }
            uint32_t bh[8][2], bl[8][2];
#pragma unroll
            for (int bt = 0; bt < 4; bt++) {
                const int nrow = warp_n * 64 + bt * 16 + (lane & 7) + ((lane >> 4) & 1) * 8;
                const int col  = kc + ((lane >> 3) & 1) * 8;
                const uint32_t off = nrow * GSTRIDE + col * 2;
                uint32_t t[4];
                ldsm_x4(t, sB_hi + off);
                bh[bt * 2][0] = t[0]; bh[bt * 2][1] = t[1];
                bh[bt * 2 + 1][0] = t[2]; bh[bt * 2 + 1][1] = t[3];
                ldsm_x4(t, sB_lo + off);
                bl[bt * 2][0] = t[0]; bl[bt * 2][1] = t[1];
                bl[bt * 2 + 1][0] = t[2]; bl[bt * 2 + 1][1] = t[3];
            }
#pragma unroll
            for (int mt = 0; mt < 2; mt++)
#pragma unroll
                for (int nt = 0; nt < 8; nt++) {
                    mma_bf16(acc[mt][nt], ah[mt], bh[nt]);
                    mma_bf16(acc[mt][nt], ah[mt], bl[nt]);
                    mma_bf16(acc[mt][nt], al[mt], bh[nt]);
                }
        }
        __syncthreads();
    }

    // -------- epilogue --------
#pragma unroll
    for (int mt = 0; mt < 2; mt++) {
        const int row0 = bm + warp_m * 32 + mt * 16 + (lane >> 2);
#pragma unroll
        for (int h = 0; h < 2; h++) {
            const int row = row0 + h * 8;
            if (row >= M) continue;
            float* dst = C + (size_t)row * N + bn + warp_n * 64 + (lane & 3) * 2;
#pragma unroll
            for (int nt = 0; nt < 8; nt++) {
                float v0 = acc[mt][nt][h * 2 + 0];
                float v1 = acc[mt][nt][h * 2 + 1];
                if (act == 1) {
                    v0 = 1.f / (1.f + expf(-v0));
                    v1 = 1.f / (1.f + expf(-v1));
                }
                *reinterpret_cast<float2*>(dst + nt * 8) = make_float2(v0, v1);
            }
        }
    }
}

// ---------------- SpMM layer 1: h = relu(A @ support1 + b1), split to bf16 ----------------
// float4 gather: 64 lanes per row, 4 rows per 256-thread block, unroll-4.
__global__ __launch_bounds__(256) void spmm_relu_split_kernel(
    const int* __restrict__ col, const float* __restrict__ val,
    const float* __restrict__ X, const float* __restrict__ bias)
{
    const int r  = blockIdx.x * 4 + (threadIdx.x >> 6);
    const int f4 = threadIdx.x & 63;                 // float4 index within row
    const float4* __restrict__ X4 = reinterpret_cast<const float4*>(X);

    const int e0 = g_rowptr[r];
    const int e1 = g_rowptr[r + 1];

    float4 a0 = make_float4(0.f, 0.f, 0.f, 0.f);
    float4 a1 = make_float4(0.f, 0.f, 0.f, 0.f);
    float4 a2 = make_float4(0.f, 0.f, 0.f, 0.f);
    float4 a3 = make_float4(0.f, 0.f, 0.f, 0.f);
    int e = e0;
    for (; e + 4 <= e1; e += 4) {
        const int   c0 = __ldg(&col[e]);
        const int   c1 = __ldg(&col[e + 1]);
        const int   c2 = __ldg(&col[e + 2]);
        const int   c3 = __ldg(&col[e + 3]);
        const float w0 = __ldg(&val[e]);
        const float w1 = __ldg(&val[e + 1]);
        const float w2 = __ldg(&val[e + 2]);
        const float w3 = __ldg(&val[e + 3]);
        const float4 v0 = X4[(size_t)c0 * 64 + f4];
        const float4 v1 = X4[(size_t)c1 * 64 + f4];
        const float4 v2 = X4[(size_t)c2 * 64 + f4];
        const float4 v3 = X4[(size_t)c3 * 64 + f4];
        a0.x = fmaf(w0, v0.x, a0.x); a0.y = fmaf(w0, v0.y, a0.y);
        a0.z = fmaf(w0, v0.z, a0.z); a0.w = fmaf(w0, v0.w, a0.w);
        a1.x = fmaf(w1, v1.x, a1.x); a1.y = fmaf(w1, v1.y, a1.y);
        a1.z = fmaf(w1, v1.z, a1.z); a1.w = fmaf(w1, v1.w, a1.w);
        a2.x = fmaf(w2, v2.x, a2.x); a2.y = fmaf(w2, v2.y, a2.y);
        a2.z = fmaf(w2, v2.z, a2.z); a2.w = fmaf(w2, v2.w, a2.w);
        a3.x = fmaf(w3, v3.x, a3.x); a3.y = fmaf(w3, v3.y, a3.y);
        a3.z = fmaf(w3, v3.z, a3.z); a3.w = fmaf(w3, v3.w, a3.w);
    }
    for (; e < e1; e++) {
        const int   c0 = __ldg(&col[e]);
        const float w0 = __ldg(&val[e]);
        const float4 v0 = X4[(size_t)c0 * 64 + f4];
        a0.x = fmaf(w0, v0.x, a0.x); a0.y = fmaf(w0, v0.y, a0.y);
        a0.z = fmaf(w0, v0.z, a0.z); a0.w = fmaf(w0, v0.w, a0.w);
    }
    const float4 b = reinterpret_cast<const float4*>(bias)[f4];
    float y0 = fmaxf(a0.x + a1.x + a2.x + a3.x + b.x, 0.f);
    float y1 = fmaxf(a0.y + a1.y + a2.y + a3.y + b.y, 0.f);
    float y2 = fmaxf(a0.z + a1.z + a2.z + a3.z + b.z, 0.f);
    float y3 = fmaxf(a0.w + a1.w + a2.w + a3.w + b.w, 0.f);

    __nv_bfloat16 h0, h1, h2, h3, l0, l1, l2, l3;
    split_f32(y0, h0, l0); split_f32(y1, h1, l1);
    split_f32(y2, h2, l2); split_f32(y3, h3, l3);
    __nv_bfloat162* hp = reinterpret_cast<__nv_bfloat162*>(g_hhi);
    __nv_bfloat162* lp = reinterpret_cast<__nv_bfloat162*>(g_hlo);
    const size_t o2 = (size_t)r * (NHID / 2) + f4 * 2;
    hp[o2 + 0] = __nv_bfloat162(h0, h1);
    hp[o2 + 1] = __nv_bfloat162(h2, h3);
    lp[o2 + 0] = __nv_bfloat162(l0, l1);
    lp[o2 + 1] = __nv_bfloat162(l2, l3);
}

// ---------------- fused z-row + edge embedding for u/v only ----------------
// Blocks [0, N_UV): zu[b] = (A@support2 + b2)[u[b]] @ We^T, split to bf16.
// Blocks [N_UV, 2*N_UV): zv[b] = (A@support2 + b2)[v[b]], split to bf16.
__global__ __launch_bounds__(NCLASS) void zuv_kernel(
    const int* __restrict__ u, const int* __restrict__ v,
    const int* __restrict__ col, const float* __restrict__ val,
    const float* __restrict__ b2, const float* __restrict__ We)
{
    const bool is_u = blockIdx.x < N_UV;
    const int b = is_u ? blockIdx.x : blockIdx.x - N_UV;
    const int r = is_u ? __ldg(&u[b]) : __ldg(&v[b]);
    const int t = threadIdx.x;            // 0..127

    const int e0 = g_rowptr[r];
    const int e1 = g_rowptr[r + 1];
    float acc0 = 0.f, acc1 = 0.f;
    int e = e0;
    for (; e + 2 <= e1; e += 2) {
        const int   c0 = __ldg(&col[e]);
        const int   c1 = __ldg(&col[e + 1]);
        const float w0 = __ldg(&val[e]);
        const float w1 = __ldg(&val[e + 1]);
        acc0 = fmaf(w0, g_support2[(size_t)c0 * NCLASS + t], acc0);
        acc1 = fmaf(w1, g_support2[(size_t)c1 * NCLASS + t], acc1);
    }
    if (e < e1) {
        acc0 = fmaf(__ldg(&val[e]), g_support2[(size_t)__ldg(&col[e]) * NCLASS + t], acc0);
    }
    const float zt = acc0 + acc1 + __ldg(&b2[t]);

    __nv_bfloat16 h, l;
    if (is_u) {
        __shared__ float zrow[NCLASS];
        zrow[t] = zt;
        __syncthreads();
        float s = 0.f;
#pragma unroll 8
        for (int k = 0; k < NCLASS; k++)
            s = fmaf(zrow[k], __ldg(&We[(size_t)t * NCLASS + k]), s);
        split_f32(s, h, l);
        g_zuhi[(size_t)b * NCLASS + t] = h;
        g_zulo[(size_t)b * NCLASS + t] = l;
    } else {
        split_f32(zt, h, l);
        g_zvhi[(size_t)b * NCLASS + t] = h;
        g_zvlo[(size_t)b * NCLASS + t] = l;
    }
}

// ---------------- launch ----------------
extern "C" void kernel_launch(void* const* d_in, const int* in_sizes, int n_in,
                              void* d_out, int out_size)
{
    const int*   u       = (const int*)d_in[0];
    const int*   v       = (const int*)d_in[1];
    const float* x       = (const float*)d_in[2];
    const int*   adj_row = (const int*)d_in[3];
    const int*   adj_col = (const int*)d_in[4];
    const float* adj_val = (const float*)d_in[5];
    const float* W1      = (const float*)d_in[6];
    const float* b1      = (const float*)d_in[7];
    const float* W2      = (const float*)d_in[8];
    const float* b2      = (const float*)d_in[9];
    const float* We      = (const float*)d_in[10];
    float* out = (float*)d_out;

    __nv_bfloat16 *xhi, *xlo, *w1th, *w1tl, *hhi, *hlo, *w2th, *w2tl, *zuh, *zul, *zvh, *zvl;
    float *support1, *support2;
    cudaGetSymbolAddress((void**)&xhi, g_xhi);
    cudaGetSymbolAddress((void**)&xlo, g_xlo);
    cudaGetSymbolAddress((void**)&w1th, g_w1t_hi);
    cudaGetSymbolAddress((void**)&w1tl, g_w1t_lo);
    cudaGetSymbolAddress((void**)&support1, g_support1);
    cudaGetSymbolAddress((void**)&hhi, g_hhi);
    cudaGetSymbolAddress((void**)&hlo, g_hlo);
    cudaGetSymbolAddress((void**)&w2th, g_w2t_hi);
    cudaGetSymbolAddress((void**)&w2tl, g_w2t_lo);
    cudaGetSymbolAddress((void**)&support2, g_support2);
    cudaGetSymbolAddress((void**)&zuh, g_zuhi);
    cudaGetSymbolAddress((void**)&zul, g_zulo);
    cudaGetSymbolAddress((void**)&zvh, g_zvhi);
    cudaGetSymbolAddress((void**)&zvl, g_zvlo);

    const int SMEM_DYN = 2 * GBUF;   // 147456 bytes
    cudaFuncSetAttribute(mma_gemm_kernel, cudaFuncAttributeMaxDynamicSharedMemorySize, SMEM_DYN);

    // 1. row pointers from sorted COO rows
    build_rowptr_kernel<<<(N_NODES + 1 + 255) / 256, 256>>>(adj_row);

    // 2. split x -> bf16 hi/lo
    {
        int n4 = (N_NODES * NFEAT) / 4;
        split4_kernel<<<(n4 + 255) / 256, 256>>>(x, xhi, xlo, n4);
    }

    // 3. transpose+split both weight matrices (single launch)
    prep_weights_kernel<<<(NFEAT * NHID + NHID * NCLASS + 255) / 256, 256>>>(W1, W2);

    // 4. support1 = x @ W1   (HMMA bf16x3)
    {
        dim3 grid(NHID / 128, (N_NODES + 127) / 128);
        mma_gemm_kernel<<<grid, 256, SMEM_DYN>>>(xhi, xlo, w1th, w1tl, support1,
                                                 N_NODES, NHID, NFEAT, 0);
    }

    // 5. h = relu(A @ support1 + b1), fused bf16 split
    spmm_relu_split_kernel<<<N_NODES / 4, 256>>>(adj_col, adj_val, support1, b1);

    // 6. support2 = h @ W2   (HMMA)
    {
        dim3 grid(NCLASS / 128, (N_NODES + 127) / 128);
        mma_gemm_kernel<<<grid, 256, SMEM_DYN>>>(hhi, hlo, w2th, w2tl, support2,
                                                 N_NODES, NCLASS, NHID, 0);
    }

    // 7+8. fused: z-rows for u/v only, + We rotation + bf16 split
    zuv_kernel<<<2 * N_UV, NCLASS>>>(u, v, adj_col, adj_val, b2, We);

    // 9. out = sigmoid(zu @ zv^T)  (HMMA, fused sigmoid)
    {
        dim3 grid(N_UV / 128, N_UV / 128);
        mma_gemm_kernel<<<grid, 256, SMEM_DYN>>>(zuh, zul, zvh, zvl, out,
                                                 N_UV, N_UV, NCLASS, 1);
    }
}